// round 15
// baseline (speedup 1.0000x reference)
#include <cuda_runtime.h>
#include <math.h>

// out = bilinear_sample(image, affine_grid(theta)) transposed to NCHW.
// Linearization term of the reference is identically zero (slope * (grid - g0) == 0).
//
// v2 smem-tile: 64x8 output tile per block, 80x16x3 smem tile (15.4KB),
// 6 blocks/SM. Gathers become conflict-free LDS instead of L1tex LDG.

constexpr int S = 1024;
constexpr int PLANE = S * S;
constexpr int TW = 64, TH = 8;        // output tile
constexpr int SW = 80, SH = 16;       // smem tile capacity per channel
constexpr int CPLANE = SW * SH;       // 1280 floats

__global__ __launch_bounds__(256, 6)
void lin_xform_1024(const float* __restrict__ image,
                    const float* __restrict__ theta,
                    float* __restrict__ out)
{
    __shared__ float tile[3 * CPLANE];   // 15360 B

    int blk = blockIdx.x;
    int twx = blk & 15;                  // 16 tiles across w
    int thy = (blk >> 4) & 127;          // 128 tiles across h
    int b   = blk >> 11;

    int w0 = twx * TW, h0 = thy * TH;
    int tid = threadIdx.x;
    int warp = tid >> 5, lane = tid & 31;

    const float* th = theta + b * 6;
    float t00 = __ldg(th + 0), t01 = __ldg(th + 1), t02 = __ldg(th + 2);
    float t10 = __ldg(th + 3), t11 = __ldg(th + 4), t12 = __ldg(th + 5);

    const float sx   = 2.0f / (float)(S - 1);
    const float half = 0.5f * (float)(S - 1);
    // ix = Ax*w + Bx*h + Cx ; iy = Ay*w + By*h + Cy
    float Ax = t00 * sx * half, Bx = t01 * sx * half;
    float Cx = (t02 + 1.0f - t00 - t01) * half;
    float Ay = t10 * sx * half, By = t11 * sx * half;
    float Cy = (t12 + 1.0f - t10 - t11) * half;

    // sample-coord bbox over this tile (extremes at rect corners)
    float wlo = (float)w0, whi = (float)(w0 + TW - 1);
    float hlo = (float)h0, hhi = (float)(h0 + TH - 1);
    float xa = fmaf(Ax, wlo, Cx), xb = fmaf(Ax, whi, Cx);
    float ya = fmaf(Ay, wlo, Cy), yb = fmaf(Ay, whi, Cy);
    float xc = Bx * hlo, xd = Bx * hhi;
    float yc = By * hlo, yd = By * hhi;
    float ixmin = fminf(xa, xb) + fminf(xc, xd);
    float ixmax = fmaxf(xa, xb) + fmaxf(xc, xd);
    float iymin = fminf(ya, yb) + fminf(yc, yd);
    float iymax = fmaxf(ya, yb) + fmaxf(yc, yd);

    int bx0 = (int)floorf(ixmin) - 1, bx1 = (int)floorf(ixmax) + 2;
    int by0 = (int)floorf(iymin) - 1, by1 = (int)floorf(iymax) + 2;
    int cx0 = max(bx0, 0), cx1 = min(bx1, S - 1);
    int cy0 = max(by0, 0), cy1 = min(by1, S - 1);

    bool fits = (cx0 <= cx1) && (cy0 <= cy1) &&
                (cx1 - cx0 < SW) && (cy1 - cy0 < SH);
    bool interior = (bx0 >= 0) && (bx1 <= S - 1) && (by0 >= 0) && (by1 <= S - 1);

    const float* imgb = image + (size_t)b * 3 * PLANE;
    float* outb = out + (size_t)b * 3 * PLANE;

    int txl = tid & 63, tyl = tid >> 6;
    int w = w0 + txl;
    float cxw = fmaf(Ax, (float)w, Cx);
    float cyw = fmaf(Ay, (float)w, Cy);

    if (fits) {
        // ---- cooperative tile load (coalesced) ----
        int lw = cx1 - cx0 + 1, lh = cy1 - cy0 + 1;   // lw<=80, lh<=16
        #pragma unroll
        for (int c = 0; c < 3; c++) {
            const float* src = imgb + c * PLANE + (cy0 << 10) + cx0;
            float* dst = tile + c * CPLANE;
            #pragma unroll
            for (int y = warp; y < 16; y += 8) {
                if (y < lh) {
                    const float* s = src + (y << 10);
                    float* d = dst + y * SW;
                    #pragma unroll
                    for (int x = lane; x < 80; x += 32)
                        if (x < lw) d[x] = __ldg(s + x);
                }
            }
        }
        __syncthreads();

        const float* qbase = tile - (cy0 * SW + cx0);

        if (interior) {
            #pragma unroll
            for (int r = 0; r < 2; r++) {
                int h = h0 + (tyl << 1) + r;
                float hf = (float)h;
                float ix = fmaf(Bx, hf, cxw);
                float iy = fmaf(By, hf, cyw);
                int x0 = __float2int_rd(ix);
                int y0 = __float2int_rd(iy);
                float wx = ix - (float)x0, wy = iy - (float)y0;
                float ox = 1.0f - wx, oy = 1.0f - wy;
                float w00 = ox * oy, w01 = wx * oy, w10 = ox * wy, w11 = wx * wy;

                const float* q = qbase + y0 * SW + x0;
                float a00 = q[0],          a01 = q[1];
                float a10 = q[SW],         a11 = q[SW + 1];
                float b00 = q[CPLANE],     b01 = q[CPLANE + 1];
                float b10 = q[CPLANE+SW],  b11 = q[CPLANE + SW + 1];
                float c00 = q[2*CPLANE],   c01 = q[2*CPLANE + 1];
                float c10 = q[2*CPLANE+SW],c11 = q[2*CPLANE + SW + 1];

                float r0 = w00 * a00;
                r0 = fmaf(w01, a01, r0); r0 = fmaf(w10, a10, r0); r0 = fmaf(w11, a11, r0);
                float r1 = w00 * b00;
                r1 = fmaf(w01, b01, r1); r1 = fmaf(w10, b10, r1); r1 = fmaf(w11, b11, r1);
                float r2 = w00 * c00;
                r2 = fmaf(w01, c01, r2); r2 = fmaf(w10, c10, r2); r2 = fmaf(w11, c11, r2);

                float* o = outb + (h << 10) + w;
                o[0] = r0; o[PLANE] = r1; o[2 * PLANE] = r2;
            }
        } else {
            // boundary tile: clamp + zero-weight semantics, taps from smem
            #pragma unroll
            for (int r = 0; r < 2; r++) {
                int h = h0 + (tyl << 1) + r;
                float hf = (float)h;
                float ix = fmaf(Bx, hf, cxw);
                float iy = fmaf(By, hf, cyw);
                int x0 = __float2int_rd(ix);
                int y0 = __float2int_rd(iy);
                float wx = ix - (float)x0, wy = iy - (float)y0;
                int x1 = x0 + 1, y1 = y0 + 1;
                bool vx0 = (unsigned)x0 < (unsigned)S;
                bool vx1 = (unsigned)x1 < (unsigned)S;
                bool vy0 = (unsigned)y0 < (unsigned)S;
                bool vy1 = (unsigned)y1 < (unsigned)S;
                float ox = 1.0f - wx, oy = 1.0f - wy;
                float w00 = (vx0 & vy0) ? ox * oy : 0.0f;
                float w01 = (vx1 & vy0) ? wx * oy : 0.0f;
                float w10 = (vx0 & vy1) ? ox * wy : 0.0f;
                float w11 = (vx1 & vy1) ? wx * wy : 0.0f;
                int x0c = min(max(x0, 0), S - 1);
                int x1c = min(max(x1, 0), S - 1);
                int y0c = min(max(y0, 0), S - 1);
                int y1c = min(max(y1, 0), S - 1);
                int i00 = y0c * SW + x0c;
                int i01 = y0c * SW + x1c;
                int i10 = y1c * SW + x0c;
                int i11 = y1c * SW + x1c;
                float r0, r1, r2;
                r0 = w00 * qbase[i00];
                r0 = fmaf(w01, qbase[i01], r0);
                r0 = fmaf(w10, qbase[i10], r0);
                r0 = fmaf(w11, qbase[i11], r0);
                r1 = w00 * qbase[CPLANE + i00];
                r1 = fmaf(w01, qbase[CPLANE + i01], r1);
                r1 = fmaf(w10, qbase[CPLANE + i10], r1);
                r1 = fmaf(w11, qbase[CPLANE + i11], r1);
                r2 = w00 * qbase[2 * CPLANE + i00];
                r2 = fmaf(w01, qbase[2 * CPLANE + i01], r2);
                r2 = fmaf(w10, qbase[2 * CPLANE + i10], r2);
                r2 = fmaf(w11, qbase[2 * CPLANE + i11], r2);
                float* o = outb + (h << 10) + w;
                o[0] = r0; o[PLANE] = r1; o[2 * PLANE] = r2;
            }
        }
    } else {
        // pathological theta: direct masked global gather
        const float* img1 = imgb + PLANE;
        #pragma unroll
        for (int r = 0; r < 2; r++) {
            int h = h0 + (tyl << 1) + r;
            float hf = (float)h;
            float ix = fmaf(Bx, hf, cxw);
            float iy = fmaf(By, hf, cyw);
            int x0 = __float2int_rd(ix);
            int y0 = __float2int_rd(iy);
            float wx = ix - (float)x0, wy = iy - (float)y0;
            int x1 = x0 + 1, y1 = y0 + 1;
            bool vx0 = (unsigned)x0 < (unsigned)S;
            bool vx1 = (unsigned)x1 < (unsigned)S;
            bool vy0 = (unsigned)y0 < (unsigned)S;
            bool vy1 = (unsigned)y1 < (unsigned)S;
            float ox = 1.0f - wx, oy = 1.0f - wy;
            float w00 = (vx0 & vy0) ? ox * oy : 0.0f;
            float w01 = (vx1 & vy0) ? wx * oy : 0.0f;
            float w10 = (vx0 & vy1) ? ox * wy : 0.0f;
            float w11 = (vx1 & vy1) ? wx * wy : 0.0f;
            int x0c = min(max(x0, 0), S - 1);
            int x1c = min(max(x1, 0), S - 1);
            int y0c = min(max(y0, 0), S - 1);
            int y1c = min(max(y1, 0), S - 1);
            int o00 = (y0c << 10) + x0c;
            int o01 = (y0c << 10) + x1c;
            int o10 = (y1c << 10) + x0c;
            int o11 = (y1c << 10) + x1c;
            float r0, r1, r2;
            r0 = w00 * __ldg(img1 - PLANE + o00);
            r0 = fmaf(w01, __ldg(img1 - PLANE + o01), r0);
            r0 = fmaf(w10, __ldg(img1 - PLANE + o10), r0);
            r0 = fmaf(w11, __ldg(img1 - PLANE + o11), r0);
            r1 = w00 * __ldg(img1 + o00);
            r1 = fmaf(w01, __ldg(img1 + o01), r1);
            r1 = fmaf(w10, __ldg(img1 + o10), r1);
            r1 = fmaf(w11, __ldg(img1 + o11), r1);
            r2 = w00 * __ldg(img1 + PLANE + o00);
            r2 = fmaf(w01, __ldg(img1 + PLANE + o01), r2);
            r2 = fmaf(w10, __ldg(img1 + PLANE + o10), r2);
            r2 = fmaf(w11, __ldg(img1 + PLANE + o11), r2);
            float* o = outb + (h << 10) + w;
            o[0] = r0; o[PLANE] = r1; o[2 * PLANE] = r2;
        }
    }
}

// ---------------- generic fallback (non-1024 shapes) ----------------
__global__ __launch_bounds__(256)
void lin_xform_generic(const float* __restrict__ image,
                       const float* __restrict__ theta,
                       float* __restrict__ out,
                       int B, int C, int Hi, int Wi, int H, int W)
{
    int row = blockIdx.x;
    int h = row % H;
    int b = row / H;
    int tid = threadIdx.x;

    const float* th = theta + b * 6;
    float t00 = __ldg(th + 0), t01 = __ldg(th + 1), t02 = __ldg(th + 2);
    float t10 = __ldg(th + 3), t11 = __ldg(th + 4), t12 = __ldg(th + 5);

    float sx = 2.0f / (float)(W - 1);
    float sy = 2.0f / (float)(H - 1);
    float Y  = fmaf((float)h, sy, -1.0f);
    float cyx = fmaf(t01, Y, t02);
    float cyy = fmaf(t11, Y, t12);
    float hxw = 0.5f * (float)(Wi - 1);
    float hyh = 0.5f * (float)(Hi - 1);

    int planeHW = Hi * Wi;
    const float* imgb = image + (size_t)b * C * planeHW;
    float* outrow = out + ((size_t)(b * C) * H + h) * W;
    size_t planeOut = (size_t)H * W;

    for (int w = tid; w < W; w += blockDim.x) {
        float X  = fmaf((float)w, sx, -1.0f);
        float ix = (fmaf(t00, X, cyx) + 1.0f) * hxw;
        float iy = (fmaf(t10, X, cyy) + 1.0f) * hyh;
        float x0f = floorf(ix), y0f = floorf(iy);
        float wx = ix - x0f, wy = iy - y0f;
        int x0 = (int)x0f, y0 = (int)y0f;
        int x1 = x0 + 1, y1 = y0 + 1;
        bool vx0 = (x0 >= 0) & (x0 < Wi);
        bool vx1 = (x1 >= 0) & (x1 < Wi);
        bool vy0 = (y0 >= 0) & (y0 < Hi);
        bool vy1 = (y1 >= 0) & (y1 < Hi);
        float ox = 1.0f - wx, oy = 1.0f - wy;
        float w00 = (vx0 & vy0) ? ox * oy : 0.0f;
        float w01 = (vx1 & vy0) ? wx * oy : 0.0f;
        float w10 = (vx0 & vy1) ? ox * wy : 0.0f;
        float w11 = (vx1 & vy1) ? wx * wy : 0.0f;
        int x0c = min(max(x0, 0), Wi - 1);
        int x1c = min(max(x1, 0), Wi - 1);
        int y0c = min(max(y0, 0), Hi - 1);
        int y1c = min(max(y1, 0), Hi - 1);
        int o00 = y0c * Wi + x0c;
        int o01 = y0c * Wi + x1c;
        int o10 = y1c * Wi + x0c;
        int o11 = y1c * Wi + x1c;
        for (int c = 0; c < C; c++) {
            const float* p = imgb + c * planeHW;
            float v = w00 * __ldg(p + o00);
            v = fmaf(w01, __ldg(p + o01), v);
            v = fmaf(w10, __ldg(p + o10), v);
            v = fmaf(w11, __ldg(p + o11), v);
            outrow[c * planeOut + w] = v;
        }
    }
}

static int isqrt_round(long long v) {
    int r = (int)(sqrt((double)v) + 0.5);
    while ((long long)r * r > v) r--;
    while ((long long)(r + 1) * (r + 1) <= v) r++;
    return r;
}

extern "C" void kernel_launch(void* const* d_in, const int* in_sizes, int n_in,
                              void* d_out, int out_size) {
    const float* image = (const float*)d_in[0];
    const float* theta = (const float*)d_in[1];
    float* out = (float*)d_out;

    int B = in_sizes[1] / 6;           // pMtrx is (B, 2, 3)
    int C = 3;
    long long imgPlane = (long long)in_sizes[0] / ((long long)B * C);
    int Hi = isqrt_round(imgPlane);
    int Wi = Hi;
    long long outPlane = (long long)out_size / ((long long)B * C);
    int H = isqrt_round(outPlane);
    int W = H;

    if (C == 3 && Hi == S && Wi == S && H == S && W == S) {
        int blocks = B * (S / TW) * (S / TH);   // B * 16 * 128 = 8192
        lin_xform_1024<<<blocks, 256>>>(image, theta, out);
    } else {
        lin_xform_generic<<<B * H, 256>>>(image, theta, out, B, C, Hi, Wi, H, W);
    }
}

// round 16
// speedup vs baseline: 1.8660x; 1.8660x over previous
#include <cuda_runtime.h>
#include <math.h>

// out = bilinear_sample(image, affine_grid(theta)) transposed to NCHW.
// Linearization term of the reference is identically zero (slope * (grid - g0) == 0).
//
// Direct scalar-gather design (proven best). 4 output rows per block for
// vertical L1 reuse; streaming stores keep L2 for the image.

constexpr int S = 1024;
constexpr int PLANE = S * S;
constexpr int ROWS_PER_BLK = 4;

__global__ __launch_bounds__(256, 4)
void lin_xform_1024(const float* __restrict__ image,
                    const float* __restrict__ theta,
                    float* __restrict__ out)
{
    int blk = blockIdx.x;                 // 0 .. B*256-1
    int h0 = (blk & (S / ROWS_PER_BLK - 1)) * ROWS_PER_BLK;
    int b  = blk / (S / ROWS_PER_BLK);
    int tid = threadIdx.x;

    const float* th = theta + b * 6;
    float t00 = __ldg(th + 0), t01 = __ldg(th + 1), t02 = __ldg(th + 2);
    float t10 = __ldg(th + 3), t11 = __ldg(th + 4), t12 = __ldg(th + 5);

    const float sx   = 2.0f / (float)(S - 1);
    const float half = 0.5f * (float)(S - 1);

    // Base on the CHANNEL-1 plane so ch0/ch2 are +/-4MB immediates.
    const float* img1 = image + (size_t)(b * 3 + 1) * PLANE;
    float* outc1 = out + (size_t)(b * 3 + 1) * PLANE;

    #pragma unroll
    for (int hh = 0; hh < ROWS_PER_BLK; hh++) {
        int h = h0 + hh;
        float Y   = fmaf((float)h, sx, -1.0f);
        float cyx = fmaf(t01, Y, t02);
        float cyy = fmaf(t11, Y, t12);
        float* out1 = outc1 + (size_t)h * S;

        #pragma unroll
        for (int k = 0; k < 4; k++) {
            int w = tid + (k << 8);

            float X  = fmaf((float)w, sx, -1.0f);
            float ix = (fmaf(t00, X, cyx) + 1.0f) * half;
            float iy = (fmaf(t10, X, cyy) + 1.0f) * half;

            int x0 = __float2int_rd(ix);
            int y0 = __float2int_rd(iy);
            float wx = ix - (float)x0;
            float wy = iy - (float)y0;
            float ox = 1.0f - wx, oy = 1.0f - wy;

            float r0, r1, r2;

            if (((unsigned)x0 < (unsigned)(S - 1)) & ((unsigned)y0 < (unsigned)(S - 1))) {
                // interior fast path: batch all 12 loads before any FMA
                const float* q = img1 + (y0 << 10) + x0;

                float a00 = __ldg(q - PLANE);
                float a01 = __ldg(q - PLANE + 1);
                float a10 = __ldg(q - PLANE + S);
                float a11 = __ldg(q - PLANE + S + 1);
                float b00 = __ldg(q);
                float b01 = __ldg(q + 1);
                float b10 = __ldg(q + S);
                float b11 = __ldg(q + S + 1);
                float c00 = __ldg(q + PLANE);
                float c01 = __ldg(q + PLANE + 1);
                float c10 = __ldg(q + PLANE + S);
                float c11 = __ldg(q + PLANE + S + 1);

                float w00 = ox * oy, w01 = wx * oy, w10 = ox * wy, w11 = wx * wy;

                r0 = w00 * a00;
                r0 = fmaf(w01, a01, r0);
                r0 = fmaf(w10, a10, r0);
                r0 = fmaf(w11, a11, r0);
                r1 = w00 * b00;
                r1 = fmaf(w01, b01, r1);
                r1 = fmaf(w10, b10, r1);
                r1 = fmaf(w11, b11, r1);
                r2 = w00 * c00;
                r2 = fmaf(w01, c01, r2);
                r2 = fmaf(w10, c10, r2);
                r2 = fmaf(w11, c11, r2);
            } else {
                // boundary path: reference semantics (clamp + zero invalid weights)
                int x1 = x0 + 1, y1 = y0 + 1;
                bool vx0 = (unsigned)x0 < (unsigned)S;
                bool vx1 = (unsigned)x1 < (unsigned)S;
                bool vy0 = (unsigned)y0 < (unsigned)S;
                bool vy1 = (unsigned)y1 < (unsigned)S;
                float w00 = (vx0 & vy0) ? ox * oy : 0.0f;
                float w01 = (vx1 & vy0) ? wx * oy : 0.0f;
                float w10 = (vx0 & vy1) ? ox * wy : 0.0f;
                float w11 = (vx1 & vy1) ? wx * wy : 0.0f;
                int x0c = min(max(x0, 0), S - 1);
                int x1c = min(max(x1, 0), S - 1);
                int y0c = min(max(y0, 0), S - 1);
                int y1c = min(max(y1, 0), S - 1);
                int o00 = (y0c << 10) + x0c;
                int o01 = (y0c << 10) + x1c;
                int o10 = (y1c << 10) + x0c;
                int o11 = (y1c << 10) + x1c;
                r0 = w00 * __ldg(img1 - PLANE + o00);
                r0 = fmaf(w01, __ldg(img1 - PLANE + o01), r0);
                r0 = fmaf(w10, __ldg(img1 - PLANE + o10), r0);
                r0 = fmaf(w11, __ldg(img1 - PLANE + o11), r0);
                r1 = w00 * __ldg(img1 + o00);
                r1 = fmaf(w01, __ldg(img1 + o01), r1);
                r1 = fmaf(w10, __ldg(img1 + o10), r1);
                r1 = fmaf(w11, __ldg(img1 + o11), r1);
                r2 = w00 * __ldg(img1 + PLANE + o00);
                r2 = fmaf(w01, __ldg(img1 + PLANE + o01), r2);
                r2 = fmaf(w10, __ldg(img1 + PLANE + o10), r2);
                r2 = fmaf(w11, __ldg(img1 + PLANE + o11), r2);
            }

            // streaming stores: output is never re-read; keep L2 for the image
            __stcs(out1 + w - PLANE, r0);
            __stcs(out1 + w,          r1);
            __stcs(out1 + w + PLANE, r2);
        }
    }
}

// ---------------- generic fallback (non-1024 shapes) ----------------
__global__ __launch_bounds__(256)
void lin_xform_generic(const float* __restrict__ image,
                       const float* __restrict__ theta,
                       float* __restrict__ out,
                       int B, int C, int Hi, int Wi, int H, int W)
{
    int row = blockIdx.x;
    int h = row % H;
    int b = row / H;
    int tid = threadIdx.x;

    const float* th = theta + b * 6;
    float t00 = __ldg(th + 0), t01 = __ldg(th + 1), t02 = __ldg(th + 2);
    float t10 = __ldg(th + 3), t11 = __ldg(th + 4), t12 = __ldg(th + 5);

    float sx = 2.0f / (float)(W - 1);
    float sy = 2.0f / (float)(H - 1);
    float Y  = fmaf((float)h, sy, -1.0f);
    float cyx = fmaf(t01, Y, t02);
    float cyy = fmaf(t11, Y, t12);
    float hxw = 0.5f * (float)(Wi - 1);
    float hyh = 0.5f * (float)(Hi - 1);

    int planeHW = Hi * Wi;
    const float* imgb = image + (size_t)b * C * planeHW;
    float* outrow = out + ((size_t)(b * C) * H + h) * W;
    size_t planeOut = (size_t)H * W;

    for (int w = tid; w < W; w += blockDim.x) {
        float X  = fmaf((float)w, sx, -1.0f);
        float ix = (fmaf(t00, X, cyx) + 1.0f) * hxw;
        float iy = (fmaf(t10, X, cyy) + 1.0f) * hyh;
        float x0f = floorf(ix), y0f = floorf(iy);
        float wx = ix - x0f, wy = iy - y0f;
        int x0 = (int)x0f, y0 = (int)y0f;
        int x1 = x0 + 1, y1 = y0 + 1;
        bool vx0 = (x0 >= 0) & (x0 < Wi);
        bool vx1 = (x1 >= 0) & (x1 < Wi);
        bool vy0 = (y0 >= 0) & (y0 < Hi);
        bool vy1 = (y1 >= 0) & (y1 < Hi);
        float ox = 1.0f - wx, oy = 1.0f - wy;
        float w00 = (vx0 & vy0) ? ox * oy : 0.0f;
        float w01 = (vx1 & vy0) ? wx * oy : 0.0f;
        float w10 = (vx0 & vy1) ? ox * wy : 0.0f;
        float w11 = (vx1 & vy1) ? wx * wy : 0.0f;
        int x0c = min(max(x0, 0), Wi - 1);
        int x1c = min(max(x1, 0), Wi - 1);
        int y0c = min(max(y0, 0), Hi - 1);
        int y1c = min(max(y1, 0), Hi - 1);
        int o00 = y0c * Wi + x0c;
        int o01 = y0c * Wi + x1c;
        int o10 = y1c * Wi + x0c;
        int o11 = y1c * Wi + x1c;
        for (int c = 0; c < C; c++) {
            const float* p = imgb + c * planeHW;
            float v = w00 * __ldg(p + o00);
            v = fmaf(w01, __ldg(p + o01), v);
            v = fmaf(w10, __ldg(p + o10), v);
            v = fmaf(w11, __ldg(p + o11), v);
            outrow[c * planeOut + w] = v;
        }
    }
}

static int isqrt_round(long long v) {
    int r = (int)(sqrt((double)v) + 0.5);
    while ((long long)r * r > v) r--;
    while ((long long)(r + 1) * (r + 1) <= v) r++;
    return r;
}

extern "C" void kernel_launch(void* const* d_in, const int* in_sizes, int n_in,
                              void* d_out, int out_size) {
    const float* image = (const float*)d_in[0];
    const float* theta = (const float*)d_in[1];
    float* out = (float*)d_out;

    int B = in_sizes[1] / 6;           // pMtrx is (B, 2, 3)
    int C = 3;
    long long imgPlane = (long long)in_sizes[0] / ((long long)B * C);
    int Hi = isqrt_round(imgPlane);
    int Wi = Hi;
    long long outPlane = (long long)out_size / ((long long)B * C);
    int H = isqrt_round(outPlane);
    int W = H;

    if (C == 3 && Hi == S && Wi == S && H == S && W == S) {
        lin_xform_1024<<<B * (S / ROWS_PER_BLK), 256>>>(image, theta, out);
    } else {
        lin_xform_generic<<<B * H, 256>>>(image, theta, out, B, C, Hi, Wi, H, W);
    }
}